// round 5
// baseline (speedup 1.0000x reference)
#include <cuda_runtime.h>
#include <math.h>

// Problem constants (fixed shapes per reference setup_inputs)
#define N_PTS   16384          // N for every array
#define NBLK    256            // KNN blocks: 128 for off-set, 128 for near-set
#define TPB     128            // threads per block; 1 query per thread
#define QPB     128            // queries per block
#define TILE    2048           // surface points per smem tile (32 KB float4)
#define NTILES  (N_PTS / TILE) // 8

#define SDF_W      7000.0f
#define EIK_W      600.0f
#define ORI_W      500.0f
#define NEAR_ORI_W 10.0f
#define GRADN_W    200.0f

// Deterministic scratch: every slot is written on every launch.
__device__ float4 g_partA[NBLK];  // (ori_contrib, sdf, eik, gradn) per block
// g_partA.x holds the relu-orientation partial of THIS block's query set
// (blocks 0..127 -> off_surface set, 128..255 -> near set)

__global__ __launch_bounds__(TPB) void knn_loss_kernel(
    const float* __restrict__ manifold_pred,   // [N,1]
    const float* __restrict__ manifold_grad,   // [N,3]
    const float* __restrict__ nonmanifold_pred,// [N,1]
    const float* __restrict__ near_pred,       // [N,1]
    const float* __restrict__ surface,         // [N,3]
    const float* __restrict__ normals,         // [N,3]
    const float* __restrict__ off_pts,         // [N,3]
    const float* __restrict__ near_pts)        // [N,3]
{
    __shared__ float4 tile[TILE];
    __shared__ float4 red[TPB];

    const int tid = threadIdx.x;
    const int b   = blockIdx.x;
    const int set = b >> 7;                 // 0: off-surface, 1: near
    const int qi  = (b & 127) * QPB + tid;  // query index within the set

    const float* __restrict__ qsrc = set ? near_pts : off_pts;
    const float qx = qsrc[3 * qi + 0];
    const float qy = qsrc[3 * qi + 1];
    const float qz = qsrc[3 * qi + 2];

    // top-2 by score = 0.5*|s|^2 - q.s  (same ranking as squared distance)
    float b1 = 3.4e38f, b2 = 3.4e38f;
    int   i1 = 0,       i2 = 0;

    for (int t = 0; t < NTILES; ++t) {
        const int tbase = t * TILE;
        // cooperative tile load: (x, y, z, 0.5*|s|^2)
        for (int j = tid; j < TILE; j += TPB) {
            const int gidx = tbase + j;
            float sx = surface[3 * gidx + 0];
            float sy = surface[3 * gidx + 1];
            float sz = surface[3 * gidx + 2];
            float h  = 0.5f * (sx * sx + sy * sy + sz * sz);
            tile[j] = make_float4(sx, sy, sz, h);
        }
        __syncthreads();

        #pragma unroll 8
        for (int j = 0; j < TILE; ++j) {
            float4 p = tile[j];
            float sc = fmaf(-qz, p.z, fmaf(-qy, p.y, fmaf(-qx, p.x, p.w)));
            if (sc < b2) {                      // rare after warm-up
                if (sc < b1) {
                    b2 = b1; i2 = i1;
                    b1 = sc; i1 = tbase + j;
                } else {
                    b2 = sc; i2 = tbase + j;
                }
            }
        }
        __syncthreads();
    }

    // gather the 2 winners, compute orientation sign
    float s1x = surface[3 * i1 + 0], s1y = surface[3 * i1 + 1], s1z = surface[3 * i1 + 2];
    float n1x = normals[3 * i1 + 0], n1y = normals[3 * i1 + 1], n1z = normals[3 * i1 + 2];
    float s2x = surface[3 * i2 + 0], s2y = surface[3 * i2 + 1], s2z = surface[3 * i2 + 2];
    float n2x = normals[3 * i2 + 0], n2y = normals[3 * i2 + 1], n2z = normals[3 * i2 + 2];

    float dot1 = (qx - s1x) * n1x + (qy - s1y) * n1y + (qz - s1z) * n1z;
    float dot2 = (qx - s2x) * n2x + (qy - s2y) * n2y + (qz - s2z) * n2z;
    float sd   = dot1 + dot2;
    float sgn  = (sd > 0.0f) ? 1.0f : ((sd < 0.0f) ? -1.0f : 0.0f);

    float pred    = set ? near_pred[qi] : nonmanifold_pred[qi];
    float contrib = fmaxf(-pred * sgn, 0.0f);

    // small losses: block b covers elements [b*64, b*64+64)
    float sdf_e = 0.0f, eik_e = 0.0f, gn_e = 0.0f;
    if (tid < 64) {
        const int e = b * 64 + tid;
        float mp = manifold_pred[e];
        sdf_e = mp * mp;
        float gx = manifold_grad[3 * e + 0];
        float gy = manifold_grad[3 * e + 1];
        float gz = manifold_grad[3 * e + 2];
        float nx = normals[3 * e + 0];
        float ny = normals[3 * e + 1];
        float nz = normals[3 * e + 2];
        float nrm = sqrtf(gx * gx + gy * gy + gz * gz) - 1.0f;
        eik_e = nrm * nrm;
        gn_e  = (gx - nx) * (gx - nx) + (gy - ny) * (gy - ny) + (gz - nz) * (gz - nz);
    }

    // deterministic block tree-reduction of 4 values
    red[tid] = make_float4(contrib, sdf_e, eik_e, gn_e);
    __syncthreads();
    for (int s = TPB / 2; s > 0; s >>= 1) {
        if (tid < s) {
            float4 a = red[tid], c = red[tid + s];
            red[tid] = make_float4(a.x + c.x, a.y + c.y, a.z + c.z, a.w + c.w);
        }
        __syncthreads();
    }
    if (tid == 0) g_partA[b] = red[0];
}

__global__ __launch_bounds__(NBLK) void finish_kernel(float* __restrict__ out)
{
    __shared__ float4 rA[NBLK];   // (ori, near_ori, sdf, eik)
    __shared__ float  rB[NBLK];   // gradn

    const int t = threadIdx.x;
    float4 p = g_partA[t];
    float ori  = (t < 128) ? p.x : 0.0f;
    float nori = (t < 128) ? 0.0f : p.x;
    rA[t] = make_float4(ori, nori, p.y, p.z);
    rB[t] = p.w;
    __syncthreads();
    for (int s = NBLK / 2; s > 0; s >>= 1) {
        if (t < s) {
            float4 a = rA[t], c = rA[t + s];
            rA[t] = make_float4(a.x + c.x, a.y + c.y, a.z + c.z, a.w + c.w);
            rB[t] += rB[t + s];
        }
        __syncthreads();
    }
    if (t == 0) {
        const float inv = 1.0f / (float)N_PTS;
        float ori_loss  = rA[0].x * inv;
        float nori_loss = rA[0].y * inv;
        float sdf_loss  = rA[0].z * inv;
        float eik_loss  = rA[0].w * inv;
        float gn_loss   = rB[0] / (3.0f * (float)N_PTS);
        float total = SDF_W * sdf_loss + EIK_W * eik_loss + ORI_W * ori_loss
                    + NEAR_ORI_W * nori_loss + GRADN_W * gn_loss;
        out[0] = total;
        out[1] = sdf_loss;
        out[2] = eik_loss;
        out[3] = ori_loss;
        out[4] = nori_loss;
        out[5] = gn_loss;
    }
}

extern "C" void kernel_launch(void* const* d_in, const int* in_sizes, int n_in,
                              void* d_out, int out_size)
{
    const float* manifold_pred    = (const float*)d_in[0];
    const float* manifold_grad    = (const float*)d_in[1];
    const float* nonmanifold_pred = (const float*)d_in[2];
    const float* near_points_pred = (const float*)d_in[3];
    const float* surface_points   = (const float*)d_in[4];
    const float* surface_normals  = (const float*)d_in[5];
    const float* off_surface_pts  = (const float*)d_in[6];
    const float* near_points      = (const float*)d_in[7];
    float* out = (float*)d_out;

    knn_loss_kernel<<<NBLK, TPB>>>(manifold_pred, manifold_grad,
                                   nonmanifold_pred, near_points_pred,
                                   surface_points, surface_normals,
                                   off_surface_pts, near_points);
    finish_kernel<<<1, NBLK>>>(out);
}

// round 6
// speedup vs baseline: 1.7650x; 1.7650x over previous
#include <cuda_runtime.h>
#include <math.h>
#include <float.h>

// Shapes fixed by reference setup_inputs
#define N_PTS    16384
#define NQ_TOT   32768            // 2 sets * 16384 queries
#define TPB      128              // threads per KNN block
#define QPT      2                // queries per thread
#define QPB      (TPB * QPT)      // 256 queries per block
#define NQG      (NQ_TOT / QPB)   // 128 query groups
#define NHALF    2                // surface split factor
#define KNN_BLK  (NQG * NHALF)    // 256 KNN blocks
#define HALF_PTS (N_PTS / NHALF)  // 8192
#define TILE     2048             // surface pts per smem tile (32KB float4)
#define TILES_PER_HALF (HALF_PTS / TILE)  // 4

#define MRG_TPB  256
#define MRG_BLK  (NQ_TOT / MRG_TPB)       // 128

#define SDF_W      7000.0f
#define EIK_W      600.0f
#define ORI_W      500.0f
#define NEAR_ORI_W 10.0f
#define GRADN_W    200.0f

// Scratch (fully rewritten every launch -> deterministic)
__device__ float4 g_cand[NHALF * NQ_TOT]; // per (half, slot): b1, b2, i1, i2
__device__ float4 g_partA[MRG_BLK];       // (ori, nori, sdf, eik)
__device__ float  g_partB[MRG_BLK];       // gradn

// Ordered top-2 insert (keeps earliest index on ties via strict <)
#define INS2(s, idx, B1, B2, I1, I2)                       \
    do {                                                   \
        if ((s) < (B1)) { B2 = B1; I2 = I1; B1 = (s); I1 = (idx); } \
        else if ((s) < (B2)) { B2 = (s); I2 = (idx); }     \
    } while (0)

__global__ __launch_bounds__(TPB) void knn_kernel(
    const float* __restrict__ surface,
    const float* __restrict__ off_pts,
    const float* __restrict__ near_pts)
{
    __shared__ float4 tile[TILE];

    const int tid  = threadIdx.x;
    const int b    = blockIdx.x;
    const int qg   = b >> 1;          // 0..127 query group
    const int half = b & 1;           // surface half
    const int slotA = qg * QPB + tid;       // global query slot
    const int slotB = slotA + TPB;
    const int set  = qg >> 6;         // 0: off-surface, 1: near

    const float* __restrict__ qsrc = set ? near_pts : off_pts;
    const int qiA = slotA & (N_PTS - 1);
    const int qiB = slotB & (N_PTS - 1);
    const float qax = qsrc[3*qiA+0], qay = qsrc[3*qiA+1], qaz = qsrc[3*qiA+2];
    const float qbx = qsrc[3*qiB+0], qby = qsrc[3*qiB+1], qbz = qsrc[3*qiB+2];

    // top-2 by score = 0.5*|s|^2 - q.s (same ranking as squared distance)
    float a1 = FLT_MAX, a2 = FLT_MAX;  int ai1 = 0, ai2 = 0;
    float c1 = FLT_MAX, c2 = FLT_MAX;  int ci1 = 0, ci2 = 0;

    const int base0 = half * HALF_PTS;
    for (int t = 0; t < TILES_PER_HALF; ++t) {
        const int tbase = base0 + t * TILE;
        for (int j = tid; j < TILE; j += TPB) {
            const int g = tbase + j;
            float sx = surface[3*g+0];
            float sy = surface[3*g+1];
            float sz = surface[3*g+2];
            tile[j] = make_float4(sx, sy, sz, 0.5f*(sx*sx + sy*sy + sz*sz));
        }
        __syncthreads();

        #pragma unroll 2
        for (int j = 0; j < TILE; j += 4) {
            float4 p0 = tile[j+0];
            float4 p1 = tile[j+1];
            float4 p2 = tile[j+2];
            float4 p3 = tile[j+3];

            // 8 independent 3-FFMA chains (4 elems x 2 queries)
            float sA0 = fmaf(-qaz, p0.z, fmaf(-qay, p0.y, fmaf(-qax, p0.x, p0.w)));
            float sA1 = fmaf(-qaz, p1.z, fmaf(-qay, p1.y, fmaf(-qax, p1.x, p1.w)));
            float sA2 = fmaf(-qaz, p2.z, fmaf(-qay, p2.y, fmaf(-qax, p2.x, p2.w)));
            float sA3 = fmaf(-qaz, p3.z, fmaf(-qay, p3.y, fmaf(-qax, p3.x, p3.w)));
            float sB0 = fmaf(-qbz, p0.z, fmaf(-qby, p0.y, fmaf(-qbx, p0.x, p0.w)));
            float sB1 = fmaf(-qbz, p1.z, fmaf(-qby, p1.y, fmaf(-qbx, p1.x, p1.w)));
            float sB2 = fmaf(-qbz, p2.z, fmaf(-qby, p2.y, fmaf(-qbx, p2.x, p2.w)));
            float sB3 = fmaf(-qbz, p3.z, fmaf(-qby, p3.y, fmaf(-qbx, p3.x, p3.w)));

            // chunk mins (FMNMX tree, alu pipe) -> one guarded test per chunk
            float mA = fminf(fminf(sA0, sA1), fminf(sA2, sA3));
            float mB = fminf(fminf(sB0, sB1), fminf(sB2, sB3));

            if (mA < a2) {                    // rare after warm-up
                INS2(sA0, tbase+j+0, a1, a2, ai1, ai2);
                INS2(sA1, tbase+j+1, a1, a2, ai1, ai2);
                INS2(sA2, tbase+j+2, a1, a2, ai1, ai2);
                INS2(sA3, tbase+j+3, a1, a2, ai1, ai2);
            }
            if (mB < c2) {
                INS2(sB0, tbase+j+0, c1, c2, ci1, ci2);
                INS2(sB1, tbase+j+1, c1, c2, ci1, ci2);
                INS2(sB2, tbase+j+2, c1, c2, ci1, ci2);
                INS2(sB3, tbase+j+3, c1, c2, ci1, ci2);
            }
        }
        __syncthreads();
    }

    g_cand[half * NQ_TOT + slotA] =
        make_float4(a1, a2, __int_as_float(ai1), __int_as_float(ai2));
    g_cand[half * NQ_TOT + slotB] =
        make_float4(c1, c2, __int_as_float(ci1), __int_as_float(ci2));
}

__global__ __launch_bounds__(MRG_TPB) void merge_kernel(
    const float* __restrict__ manifold_pred,
    const float* __restrict__ manifold_grad,
    const float* __restrict__ nonmanifold_pred,
    const float* __restrict__ near_pred,
    const float* __restrict__ surface,
    const float* __restrict__ normals,
    const float* __restrict__ off_pts,
    const float* __restrict__ near_pts)
{
    __shared__ float4 rA[MRG_TPB];
    __shared__ float  rB[MRG_TPB];

    const int tid  = threadIdx.x;
    const int slot = blockIdx.x * MRG_TPB + tid;

    // merge two sorted top-2 pairs; prefer half 0 (lower indices) on ties
    float4 h0 = g_cand[slot];
    float4 h1 = g_cand[NQ_TOT + slot];
    int j1, j2;
    if (h0.x <= h1.x) {
        j1 = __float_as_int(h0.z);
        j2 = (h0.y <= h1.x) ? __float_as_int(h0.w) : __float_as_int(h1.z);
    } else {
        j1 = __float_as_int(h1.z);
        j2 = (h1.y <  h0.x) ? __float_as_int(h1.w) : __float_as_int(h0.z);
    }

    const int set = slot >> 14;
    const int qi  = slot & (N_PTS - 1);
    const float* __restrict__ qsrc = set ? near_pts : off_pts;
    const float qx = qsrc[3*qi+0], qy = qsrc[3*qi+1], qz = qsrc[3*qi+2];

    float s1x = surface[3*j1+0], s1y = surface[3*j1+1], s1z = surface[3*j1+2];
    float n1x = normals[3*j1+0], n1y = normals[3*j1+1], n1z = normals[3*j1+2];
    float s2x = surface[3*j2+0], s2y = surface[3*j2+1], s2z = surface[3*j2+2];
    float n2x = normals[3*j2+0], n2y = normals[3*j2+1], n2z = normals[3*j2+2];

    float dot1 = (qx-s1x)*n1x + (qy-s1y)*n1y + (qz-s1z)*n1z;
    float dot2 = (qx-s2x)*n2x + (qy-s2y)*n2y + (qz-s2z)*n2z;
    float sd   = dot1 + dot2;
    float sgn  = (sd > 0.0f) ? 1.0f : ((sd < 0.0f) ? -1.0f : 0.0f);

    float pred    = set ? near_pred[qi] : nonmanifold_pred[qi];
    float contrib = fmaxf(-pred * sgn, 0.0f);
    float ori  = set ? 0.0f : contrib;
    float nori = set ? contrib : 0.0f;

    // small losses: set-0 slots cover elements 0..16383 exactly once
    float sdf_e = 0.0f, eik_e = 0.0f, gn_e = 0.0f;
    if (slot < N_PTS) {
        const int e = slot;
        float mp = manifold_pred[e];
        sdf_e = mp * mp;
        float gx = manifold_grad[3*e+0], gy = manifold_grad[3*e+1], gz = manifold_grad[3*e+2];
        float nx = normals[3*e+0],       ny = normals[3*e+1],       nz = normals[3*e+2];
        float nrm = sqrtf(gx*gx + gy*gy + gz*gz) - 1.0f;
        eik_e = nrm * nrm;
        gn_e  = (gx-nx)*(gx-nx) + (gy-ny)*(gy-ny) + (gz-nz)*(gz-nz);
    }

    rA[tid] = make_float4(ori, nori, sdf_e, eik_e);
    rB[tid] = gn_e;
    __syncthreads();
    for (int s = MRG_TPB / 2; s > 0; s >>= 1) {
        if (tid < s) {
            float4 a = rA[tid], c = rA[tid + s];
            rA[tid] = make_float4(a.x + c.x, a.y + c.y, a.z + c.z, a.w + c.w);
            rB[tid] += rB[tid + s];
        }
        __syncthreads();
    }
    if (tid == 0) { g_partA[blockIdx.x] = rA[0]; g_partB[blockIdx.x] = rB[0]; }
}

__global__ __launch_bounds__(MRG_BLK) void finish_kernel(float* __restrict__ out)
{
    __shared__ float4 rA[MRG_BLK];
    __shared__ float  rB[MRG_BLK];
    const int t = threadIdx.x;
    rA[t] = g_partA[t];
    rB[t] = g_partB[t];
    __syncthreads();
    for (int s = MRG_BLK / 2; s > 0; s >>= 1) {
        if (t < s) {
            float4 a = rA[t], c = rA[t + s];
            rA[t] = make_float4(a.x + c.x, a.y + c.y, a.z + c.z, a.w + c.w);
            rB[t] += rB[t + s];
        }
        __syncthreads();
    }
    if (t == 0) {
        const float inv = 1.0f / (float)N_PTS;
        float ori_loss  = rA[0].x * inv;
        float nori_loss = rA[0].y * inv;
        float sdf_loss  = rA[0].z * inv;
        float eik_loss  = rA[0].w * inv;
        float gn_loss   = rB[0] / (3.0f * (float)N_PTS);
        float total = SDF_W * sdf_loss + EIK_W * eik_loss + ORI_W * ori_loss
                    + NEAR_ORI_W * nori_loss + GRADN_W * gn_loss;
        out[0] = total;
        out[1] = sdf_loss;
        out[2] = eik_loss;
        out[3] = ori_loss;
        out[4] = nori_loss;
        out[5] = gn_loss;
    }
}

extern "C" void kernel_launch(void* const* d_in, const int* in_sizes, int n_in,
                              void* d_out, int out_size)
{
    const float* manifold_pred    = (const float*)d_in[0];
    const float* manifold_grad    = (const float*)d_in[1];
    const float* nonmanifold_pred = (const float*)d_in[2];
    const float* near_points_pred = (const float*)d_in[3];
    const float* surface_points   = (const float*)d_in[4];
    const float* surface_normals  = (const float*)d_in[5];
    const float* off_surface_pts  = (const float*)d_in[6];
    const float* near_points      = (const float*)d_in[7];
    float* out = (float*)d_out;

    knn_kernel<<<KNN_BLK, TPB>>>(surface_points, off_surface_pts, near_points);
    merge_kernel<<<MRG_BLK, MRG_TPB>>>(manifold_pred, manifold_grad,
                                       nonmanifold_pred, near_points_pred,
                                       surface_points, surface_normals,
                                       off_surface_pts, near_points);
    finish_kernel<<<1, MRG_BLK>>>(out);
}

// round 7
// speedup vs baseline: 2.3129x; 1.3104x over previous
#include <cuda_runtime.h>
#include <math.h>
#include <float.h>

// Shapes fixed by reference setup_inputs
#define N_PTS    16384
#define NQ_TOT   32768            // 2 sets * 16384 queries
#define TPB      128              // threads per KNN block
#define QPT      2                // queries per thread
#define QPB      (TPB * QPT)      // 256 queries per block
#define NQG      (NQ_TOT / QPB)   // 128 query groups
#define NHALF    4                // surface split factor
#define KNN_BLK  (NQG * NHALF)    // 512 KNN blocks
#define HALF_PTS (N_PTS / NHALF)  // 4096
#define TILE     2048             // surface pts per smem tile
#define TILES_PER_HALF (HALF_PTS / TILE)  // 2
#define PAIRS    (TILE / 2)       // 1024 packed pairs per tile

#define MRG_TPB  256
#define MRG_BLK  (NQ_TOT / MRG_TPB)       // 128

#define SDF_W      7000.0f
#define EIK_W      600.0f
#define ORI_W      500.0f
#define NEAR_ORI_W 10.0f
#define GRADN_W    200.0f

// Scratch (fully rewritten every launch -> deterministic)
__device__ float4 g_cand[NHALF * NQ_TOT]; // per (half, slot): b1, b2, i1, i2
__device__ float4 g_partA[MRG_BLK];       // (ori, nori, sdf, eik)
__device__ float  g_partB[MRG_BLK];       // gradn

typedef unsigned long long u64;

__device__ __forceinline__ u64 pack2(float lo, float hi) {
    u64 r;
    asm("mov.b64 %0, {%1, %2};" : "=l"(r) : "f"(lo), "f"(hi));
    return r;
}
__device__ __forceinline__ void unpack2(u64 v, float& lo, float& hi) {
    asm("mov.b64 {%0, %1}, %2;" : "=f"(lo), "=f"(hi) : "l"(v));
}
// packed dual FMA: d = a*b + c on two f32 lanes (sm_100+ only, PTX-only)
__device__ __forceinline__ u64 ffma2(u64 a, u64 b, u64 c) {
    u64 d;
    asm("fma.rn.f32x2 %0, %1, %2, %3;" : "=l"(d) : "l"(a), "l"(b), "l"(c));
    return d;
}

// Ordered top-2 insert (strict < keeps earliest index on ties)
#define INS2(s, idx, B1, B2, I1, I2)                                \
    do {                                                            \
        if ((s) < (B1)) { B2 = B1; I2 = I1; B1 = (s); I1 = (idx); } \
        else if ((s) < (B2)) { B2 = (s); I2 = (idx); }              \
    } while (0)

__global__ __launch_bounds__(TPB) void knn_kernel(
    const float* __restrict__ surface,
    const float* __restrict__ off_pts,
    const float* __restrict__ near_pts)
{
    // packed pair tiles: tileA[p] = {pack(x0,x1), pack(y0,y1)}
    //                    tileB[p] = {pack(z0,z1), pack(h0,h1)}, h = 0.5*|s|^2
    __shared__ ulonglong2 tileA[PAIRS];
    __shared__ ulonglong2 tileB[PAIRS];

    const int tid  = threadIdx.x;
    const int b    = blockIdx.x;
    const int qg   = b >> 2;          // 0..127 query group
    const int half = b & 3;           // surface quarter
    const int slotA = qg * QPB + tid;
    const int slotB = slotA + TPB;
    const int set  = qg >> 6;         // 0: off-surface, 1: near

    const float* __restrict__ qsrc = set ? near_pts : off_pts;
    const int qiA = slotA & (N_PTS - 1);
    const int qiB = slotB & (N_PTS - 1);
    const float qax = qsrc[3*qiA+0], qay = qsrc[3*qiA+1], qaz = qsrc[3*qiA+2];
    const float qbx = qsrc[3*qiB+0], qby = qsrc[3*qiB+1], qbz = qsrc[3*qiB+2];

    // broadcast packed negated query coeffs
    const u64 nax = pack2(-qax, -qax), nay = pack2(-qay, -qay), naz = pack2(-qaz, -qaz);
    const u64 nbx = pack2(-qbx, -qbx), nby = pack2(-qby, -qby), nbz = pack2(-qbz, -qbz);

    // top-2 by score = 0.5*|s|^2 - q.s (same ranking as squared distance)
    float a1 = FLT_MAX, a2 = FLT_MAX;  int ai1 = 0, ai2 = 0;
    float c1 = FLT_MAX, c2 = FLT_MAX;  int ci1 = 0, ci2 = 0;

    const int base0 = half * HALF_PTS;
    for (int t = 0; t < TILES_PER_HALF; ++t) {
        const int tbase = base0 + t * TILE;
        for (int p = tid; p < PAIRS; p += TPB) {
            const int g = tbase + 2 * p;
            float x0 = surface[3*g+0], y0 = surface[3*g+1], z0 = surface[3*g+2];
            float x1 = surface[3*g+3], y1 = surface[3*g+4], z1 = surface[3*g+5];
            float h0 = 0.5f * (x0*x0 + y0*y0 + z0*z0);
            float h1 = 0.5f * (x1*x1 + y1*y1 + z1*z1);
            ulonglong2 A, B;
            A.x = pack2(x0, x1); A.y = pack2(y0, y1);
            B.x = pack2(z0, z1); B.y = pack2(h0, h1);
            tileA[p] = A; tileB[p] = B;
        }
        __syncthreads();

        #pragma unroll 2
        for (int p = 0; p < PAIRS; p += 2) {
            ulonglong2 A0 = tileA[p+0];
            ulonglong2 B0 = tileB[p+0];
            ulonglong2 A1 = tileA[p+1];
            ulonglong2 B1 = tileB[p+1];

            // 4 independent packed 3-FFMA2 chains (8 elements of work)
            u64 sA01 = ffma2(naz, B0.x, ffma2(nay, A0.y, ffma2(nax, A0.x, B0.y)));
            u64 sA23 = ffma2(naz, B1.x, ffma2(nay, A1.y, ffma2(nax, A1.x, B1.y)));
            u64 sB01 = ffma2(nbz, B0.x, ffma2(nby, A0.y, ffma2(nbx, A0.x, B0.y)));
            u64 sB23 = ffma2(nbz, B1.x, ffma2(nby, A1.y, ffma2(nbx, A1.x, B1.y)));

            float a0f, a1f, a2f, a3f, b0f, b1f, b2f, b3f;
            unpack2(sA01, a0f, a1f); unpack2(sA23, a2f, a3f);
            unpack2(sB01, b0f, b1f); unpack2(sB23, b2f, b3f);

            float mA = fminf(fminf(a0f, a1f), fminf(a2f, a3f));
            float mB = fminf(fminf(b0f, b1f), fminf(b2f, b3f));

            const int e = tbase + 2 * p;
            if (mA < a2) {                    // rare after warm-up
                INS2(a0f, e+0, a1, a2, ai1, ai2);
                INS2(a1f, e+1, a1, a2, ai1, ai2);
                INS2(a2f, e+2, a1, a2, ai1, ai2);
                INS2(a3f, e+3, a1, a2, ai1, ai2);
            }
            if (mB < c2) {
                INS2(b0f, e+0, c1, c2, ci1, ci2);
                INS2(b1f, e+1, c1, c2, ci1, ci2);
                INS2(b2f, e+2, c1, c2, ci1, ci2);
                INS2(b3f, e+3, c1, c2, ci1, ci2);
            }
        }
        __syncthreads();
    }

    g_cand[half * NQ_TOT + slotA] =
        make_float4(a1, a2, __int_as_float(ai1), __int_as_float(ai2));
    g_cand[half * NQ_TOT + slotB] =
        make_float4(c1, c2, __int_as_float(ci1), __int_as_float(ci2));
}

__global__ __launch_bounds__(MRG_TPB) void merge_kernel(
    const float* __restrict__ manifold_pred,
    const float* __restrict__ manifold_grad,
    const float* __restrict__ nonmanifold_pred,
    const float* __restrict__ near_pred,
    const float* __restrict__ surface,
    const float* __restrict__ normals,
    const float* __restrict__ off_pts,
    const float* __restrict__ near_pts)
{
    __shared__ float4 rA[MRG_TPB];
    __shared__ float  rB[MRG_TPB];

    const int tid  = threadIdx.x;
    const int slot = blockIdx.x * MRG_TPB + tid;

    // merge 4 sorted top-2 pairs (in half order -> earliest index wins ties)
    float b1 = FLT_MAX, b2 = FLT_MAX; int j1 = 0, j2 = 0;
    #pragma unroll
    for (int h = 0; h < NHALF; ++h) {
        float4 c = g_cand[h * NQ_TOT + slot];
        int ci1 = __float_as_int(c.z), ci2 = __float_as_int(c.w);
        INS2(c.x, ci1, b1, b2, j1, j2);
        INS2(c.y, ci2, b1, b2, j1, j2);
    }

    const int set = slot >> 14;
    const int qi  = slot & (N_PTS - 1);
    const float* __restrict__ qsrc = set ? near_pts : off_pts;
    const float qx = qsrc[3*qi+0], qy = qsrc[3*qi+1], qz = qsrc[3*qi+2];

    float s1x = surface[3*j1+0], s1y = surface[3*j1+1], s1z = surface[3*j1+2];
    float n1x = normals[3*j1+0], n1y = normals[3*j1+1], n1z = normals[3*j1+2];
    float s2x = surface[3*j2+0], s2y = surface[3*j2+1], s2z = surface[3*j2+2];
    float n2x = normals[3*j2+0], n2y = normals[3*j2+1], n2z = normals[3*j2+2];

    float dot1 = (qx-s1x)*n1x + (qy-s1y)*n1y + (qz-s1z)*n1z;
    float dot2 = (qx-s2x)*n2x + (qy-s2y)*n2y + (qz-s2z)*n2z;
    float sd   = dot1 + dot2;
    float sgn  = (sd > 0.0f) ? 1.0f : ((sd < 0.0f) ? -1.0f : 0.0f);

    float pred    = set ? near_pred[qi] : nonmanifold_pred[qi];
    float contrib = fmaxf(-pred * sgn, 0.0f);
    float ori  = set ? 0.0f : contrib;
    float nori = set ? contrib : 0.0f;

    // small losses: set-0 slots cover elements 0..16383 exactly once
    float sdf_e = 0.0f, eik_e = 0.0f, gn_e = 0.0f;
    if (slot < N_PTS) {
        const int e = slot;
        float mp = manifold_pred[e];
        sdf_e = mp * mp;
        float gx = manifold_grad[3*e+0], gy = manifold_grad[3*e+1], gz = manifold_grad[3*e+2];
        float nx = normals[3*e+0],       ny = normals[3*e+1],       nz = normals[3*e+2];
        float nrm = sqrtf(gx*gx + gy*gy + gz*gz) - 1.0f;
        eik_e = nrm * nrm;
        gn_e  = (gx-nx)*(gx-nx) + (gy-ny)*(gy-ny) + (gz-nz)*(gz-nz);
    }

    rA[tid] = make_float4(ori, nori, sdf_e, eik_e);
    rB[tid] = gn_e;
    __syncthreads();
    for (int s = MRG_TPB / 2; s > 0; s >>= 1) {
        if (tid < s) {
            float4 a = rA[tid], c = rA[tid + s];
            rA[tid] = make_float4(a.x + c.x, a.y + c.y, a.z + c.z, a.w + c.w);
            rB[tid] += rB[tid + s];
        }
        __syncthreads();
    }
    if (tid == 0) { g_partA[blockIdx.x] = rA[0]; g_partB[blockIdx.x] = rB[0]; }
}

__global__ __launch_bounds__(MRG_BLK) void finish_kernel(float* __restrict__ out)
{
    __shared__ float4 rA[MRG_BLK];
    __shared__ float  rB[MRG_BLK];
    const int t = threadIdx.x;
    rA[t] = g_partA[t];
    rB[t] = g_partB[t];
    __syncthreads();
    for (int s = MRG_BLK / 2; s > 0; s >>= 1) {
        if (t < s) {
            float4 a = rA[t], c = rA[t + s];
            rA[t] = make_float4(a.x + c.x, a.y + c.y, a.z + c.z, a.w + c.w);
            rB[t] += rB[t + s];
        }
        __syncthreads();
    }
    if (t == 0) {
        const float inv = 1.0f / (float)N_PTS;
        float ori_loss  = rA[0].x * inv;
        float nori_loss = rA[0].y * inv;
        float sdf_loss  = rA[0].z * inv;
        float eik_loss  = rA[0].w * inv;
        float gn_loss   = rB[0] / (3.0f * (float)N_PTS);
        float total = SDF_W * sdf_loss + EIK_W * eik_loss + ORI_W * ori_loss
                    + NEAR_ORI_W * nori_loss + GRADN_W * gn_loss;
        out[0] = total;
        out[1] = sdf_loss;
        out[2] = eik_loss;
        out[3] = ori_loss;
        out[4] = nori_loss;
        out[5] = gn_loss;
    }
}

extern "C" void kernel_launch(void* const* d_in, const int* in_sizes, int n_in,
                              void* d_out, int out_size)
{
    const float* manifold_pred    = (const float*)d_in[0];
    const float* manifold_grad    = (const float*)d_in[1];
    const float* nonmanifold_pred = (const float*)d_in[2];
    const float* near_points_pred = (const float*)d_in[3];
    const float* surface_points   = (const float*)d_in[4];
    const float* surface_normals  = (const float*)d_in[5];
    const float* off_surface_pts  = (const float*)d_in[6];
    const float* near_points      = (const float*)d_in[7];
    float* out = (float*)d_out;

    knn_kernel<<<KNN_BLK, TPB>>>(surface_points, off_surface_pts, near_points);
    merge_kernel<<<MRG_BLK, MRG_TPB>>>(manifold_pred, manifold_grad,
                                       nonmanifold_pred, near_points_pred,
                                       surface_points, surface_normals,
                                       off_surface_pts, near_points);
    finish_kernel<<<1, MRG_BLK>>>(out);
}

// round 8
// speedup vs baseline: 2.4316x; 1.0513x over previous
#include <cuda_runtime.h>
#include <math.h>
#include <float.h>

// Shapes fixed by reference setup_inputs
#define N_PTS    16384
#define NQ_TOT   32768            // 2 sets * 16384 queries
#define TPB      128              // threads per KNN block
#define QPT      2                // queries per thread
#define QPB      (TPB * QPT)      // 256 queries per block
#define NQG      (NQ_TOT / QPB)   // 128 query groups
#define NHALF    8                // surface split factor
#define KNN_BLK  (NQG * NHALF)    // 1024 KNN blocks (fully resident: 148*8 >= 1024)
#define HALF_PTS (N_PTS / NHALF)  // 2048
#define TILE     1024             // surface pts per smem tile (16KB) -> 8 blocks/SM
#define TILES_PER_HALF (HALF_PTS / TILE)  // 2
#define PAIRS    (TILE / 2)       // 512 packed pairs per tile

#define MRG_TPB  256
#define MRG_BLK  (NQ_TOT / MRG_TPB)       // 128

#define SDF_W      7000.0f
#define EIK_W      600.0f
#define ORI_W      500.0f
#define NEAR_ORI_W 10.0f
#define GRADN_W    200.0f

// Scratch (fully rewritten every launch -> deterministic)
__device__ float4 g_cand[NHALF * NQ_TOT]; // per (half, slot): b1, b2, i1, i2
__device__ float4 g_partA[MRG_BLK];       // (ori, nori, sdf, eik)
__device__ float  g_partB[MRG_BLK];       // gradn

typedef unsigned long long u64;

__device__ __forceinline__ u64 pack2(float lo, float hi) {
    u64 r;
    asm("mov.b64 %0, {%1, %2};" : "=l"(r) : "f"(lo), "f"(hi));
    return r;
}
__device__ __forceinline__ void unpack2(u64 v, float& lo, float& hi) {
    asm("mov.b64 {%0, %1}, %2;" : "=f"(lo), "=f"(hi) : "l"(v));
}
// packed dual FMA: d = a*b + c on two f32 lanes (sm_100+ only, PTX-only)
__device__ __forceinline__ u64 ffma2(u64 a, u64 b, u64 c) {
    u64 d;
    asm("fma.rn.f32x2 %0, %1, %2, %3;" : "=l"(d) : "l"(a), "l"(b), "l"(c));
    return d;
}

// Ordered top-2 insert (strict < keeps earliest index on ties)
#define INS2(s, idx, B1, B2, I1, I2)                                \
    do {                                                            \
        if ((s) < (B1)) { B2 = B1; I2 = I1; B1 = (s); I1 = (idx); } \
        else if ((s) < (B2)) { B2 = (s); I2 = (idx); }              \
    } while (0)

__global__ __launch_bounds__(TPB) void knn_kernel(
    const float* __restrict__ surface,
    const float* __restrict__ off_pts,
    const float* __restrict__ near_pts)
{
    // packed pair tiles: tileA[p] = {pack(x0,x1), pack(y0,y1)}
    //                    tileB[p] = {pack(z0,z1), pack(h0,h1)}, h = 0.5*|s|^2
    __shared__ ulonglong2 tileA[PAIRS];
    __shared__ ulonglong2 tileB[PAIRS];

    const int tid  = threadIdx.x;
    const int b    = blockIdx.x;
    const int qg   = b >> 3;          // 0..127 query group
    const int half = b & 7;           // surface eighth
    const int slotA = qg * QPB + tid;
    const int slotB = slotA + TPB;
    const int set  = qg >> 6;         // 0: off-surface, 1: near

    const float* __restrict__ qsrc = set ? near_pts : off_pts;
    const int qiA = slotA & (N_PTS - 1);
    const int qiB = slotB & (N_PTS - 1);
    const float qax = qsrc[3*qiA+0], qay = qsrc[3*qiA+1], qaz = qsrc[3*qiA+2];
    const float qbx = qsrc[3*qiB+0], qby = qsrc[3*qiB+1], qbz = qsrc[3*qiB+2];

    // broadcast packed negated query coeffs
    const u64 nax = pack2(-qax, -qax), nay = pack2(-qay, -qay), naz = pack2(-qaz, -qaz);
    const u64 nbx = pack2(-qbx, -qbx), nby = pack2(-qby, -qby), nbz = pack2(-qbz, -qbz);

    // top-2 by score = 0.5*|s|^2 - q.s (same ranking as squared distance)
    float a1 = FLT_MAX, a2 = FLT_MAX;  int ai1 = 0, ai2 = 0;
    float c1 = FLT_MAX, c2 = FLT_MAX;  int ci1 = 0, ci2 = 0;

    const int base0 = half * HALF_PTS;
    for (int t = 0; t < TILES_PER_HALF; ++t) {
        const int tbase = base0 + t * TILE;
        for (int p = tid; p < PAIRS; p += TPB) {
            const int g = tbase + 2 * p;
            float x0 = surface[3*g+0], y0 = surface[3*g+1], z0 = surface[3*g+2];
            float x1 = surface[3*g+3], y1 = surface[3*g+4], z1 = surface[3*g+5];
            float h0 = 0.5f * (x0*x0 + y0*y0 + z0*z0);
            float h1 = 0.5f * (x1*x1 + y1*y1 + z1*z1);
            ulonglong2 A, B;
            A.x = pack2(x0, x1); A.y = pack2(y0, y1);
            B.x = pack2(z0, z1); B.y = pack2(h0, h1);
            tileA[p] = A; tileB[p] = B;
        }
        __syncthreads();

        #pragma unroll 2
        for (int p = 0; p < PAIRS; p += 2) {
            ulonglong2 A0 = tileA[p+0];
            ulonglong2 B0 = tileB[p+0];
            ulonglong2 A1 = tileA[p+1];
            ulonglong2 B1 = tileB[p+1];

            // 4 independent packed 3-FFMA2 chains (8 elements of work)
            u64 sA01 = ffma2(naz, B0.x, ffma2(nay, A0.y, ffma2(nax, A0.x, B0.y)));
            u64 sA23 = ffma2(naz, B1.x, ffma2(nay, A1.y, ffma2(nax, A1.x, B1.y)));
            u64 sB01 = ffma2(nbz, B0.x, ffma2(nby, A0.y, ffma2(nbx, A0.x, B0.y)));
            u64 sB23 = ffma2(nbz, B1.x, ffma2(nby, A1.y, ffma2(nbx, A1.x, B1.y)));

            float a0f, a1f, a2f, a3f, b0f, b1f, b2f, b3f;
            unpack2(sA01, a0f, a1f); unpack2(sA23, a2f, a3f);
            unpack2(sB01, b0f, b1f); unpack2(sB23, b2f, b3f);

            float mA = fminf(fminf(a0f, a1f), fminf(a2f, a3f));
            float mB = fminf(fminf(b0f, b1f), fminf(b2f, b3f));

            const int e = tbase + 2 * p;
            if (mA < a2) {
                INS2(a0f, e+0, a1, a2, ai1, ai2);
                INS2(a1f, e+1, a1, a2, ai1, ai2);
                INS2(a2f, e+2, a1, a2, ai1, ai2);
                INS2(a3f, e+3, a1, a2, ai1, ai2);
            }
            if (mB < c2) {
                INS2(b0f, e+0, c1, c2, ci1, ci2);
                INS2(b1f, e+1, c1, c2, ci1, ci2);
                INS2(b2f, e+2, c1, c2, ci1, ci2);
                INS2(b3f, e+3, c1, c2, ci1, ci2);
            }
        }
        __syncthreads();
    }

    g_cand[half * NQ_TOT + slotA] =
        make_float4(a1, a2, __int_as_float(ai1), __int_as_float(ai2));
    g_cand[half * NQ_TOT + slotB] =
        make_float4(c1, c2, __int_as_float(ci1), __int_as_float(ci2));
}

__global__ __launch_bounds__(MRG_TPB) void merge_kernel(
    const float* __restrict__ manifold_pred,
    const float* __restrict__ manifold_grad,
    const float* __restrict__ nonmanifold_pred,
    const float* __restrict__ near_pred,
    const float* __restrict__ surface,
    const float* __restrict__ normals,
    const float* __restrict__ off_pts,
    const float* __restrict__ near_pts)
{
    __shared__ float4 rA[MRG_TPB];
    __shared__ float  rB[MRG_TPB];

    const int tid  = threadIdx.x;
    const int slot = blockIdx.x * MRG_TPB + tid;

    // merge 8 sorted top-2 pairs (in half order -> earliest index wins ties)
    float b1 = FLT_MAX, b2 = FLT_MAX; int j1 = 0, j2 = 0;
    #pragma unroll
    for (int h = 0; h < NHALF; ++h) {
        float4 c = g_cand[h * NQ_TOT + slot];
        int ci1 = __float_as_int(c.z), ci2 = __float_as_int(c.w);
        INS2(c.x, ci1, b1, b2, j1, j2);
        INS2(c.y, ci2, b1, b2, j1, j2);
    }

    const int set = slot >> 14;
    const int qi  = slot & (N_PTS - 1);
    const float* __restrict__ qsrc = set ? near_pts : off_pts;
    const float qx = qsrc[3*qi+0], qy = qsrc[3*qi+1], qz = qsrc[3*qi+2];

    float s1x = surface[3*j1+0], s1y = surface[3*j1+1], s1z = surface[3*j1+2];
    float n1x = normals[3*j1+0], n1y = normals[3*j1+1], n1z = normals[3*j1+2];
    float s2x = surface[3*j2+0], s2y = surface[3*j2+1], s2z = surface[3*j2+2];
    float n2x = normals[3*j2+0], n2y = normals[3*j2+1], n2z = normals[3*j2+2];

    float dot1 = (qx-s1x)*n1x + (qy-s1y)*n1y + (qz-s1z)*n1z;
    float dot2 = (qx-s2x)*n2x + (qy-s2y)*n2y + (qz-s2z)*n2z;
    float sd   = dot1 + dot2;
    float sgn  = (sd > 0.0f) ? 1.0f : ((sd < 0.0f) ? -1.0f : 0.0f);

    float pred    = set ? near_pred[qi] : nonmanifold_pred[qi];
    float contrib = fmaxf(-pred * sgn, 0.0f);
    float ori  = set ? 0.0f : contrib;
    float nori = set ? contrib : 0.0f;

    // small losses: set-0 slots cover elements 0..16383 exactly once
    float sdf_e = 0.0f, eik_e = 0.0f, gn_e = 0.0f;
    if (slot < N_PTS) {
        const int e = slot;
        float mp = manifold_pred[e];
        sdf_e = mp * mp;
        float gx = manifold_grad[3*e+0], gy = manifold_grad[3*e+1], gz = manifold_grad[3*e+2];
        float nx = normals[3*e+0],       ny = normals[3*e+1],       nz = normals[3*e+2];
        float nrm = sqrtf(gx*gx + gy*gy + gz*gz) - 1.0f;
        eik_e = nrm * nrm;
        gn_e  = (gx-nx)*(gx-nx) + (gy-ny)*(gy-ny) + (gz-nz)*(gz-nz);
    }

    rA[tid] = make_float4(ori, nori, sdf_e, eik_e);
    rB[tid] = gn_e;
    __syncthreads();
    for (int s = MRG_TPB / 2; s > 0; s >>= 1) {
        if (tid < s) {
            float4 a = rA[tid], c = rA[tid + s];
            rA[tid] = make_float4(a.x + c.x, a.y + c.y, a.z + c.z, a.w + c.w);
            rB[tid] += rB[tid + s];
        }
        __syncthreads();
    }
    if (tid == 0) { g_partA[blockIdx.x] = rA[0]; g_partB[blockIdx.x] = rB[0]; }
}

__global__ __launch_bounds__(MRG_BLK) void finish_kernel(float* __restrict__ out)
{
    __shared__ float4 rA[MRG_BLK];
    __shared__ float  rB[MRG_BLK];
    const int t = threadIdx.x;
    rA[t] = g_partA[t];
    rB[t] = g_partB[t];
    __syncthreads();
    for (int s = MRG_BLK / 2; s > 0; s >>= 1) {
        if (t < s) {
            float4 a = rA[t], c = rA[t + s];
            rA[t] = make_float4(a.x + c.x, a.y + c.y, a.z + c.z, a.w + c.w);
            rB[t] += rB[t + s];
        }
        __syncthreads();
    }
    if (t == 0) {
        const float inv = 1.0f / (float)N_PTS;
        float ori_loss  = rA[0].x * inv;
        float nori_loss = rA[0].y * inv;
        float sdf_loss  = rA[0].z * inv;
        float eik_loss  = rA[0].w * inv;
        float gn_loss   = rB[0] / (3.0f * (float)N_PTS);
        float total = SDF_W * sdf_loss + EIK_W * eik_loss + ORI_W * ori_loss
                    + NEAR_ORI_W * nori_loss + GRADN_W * gn_loss;
        out[0] = total;
        out[1] = sdf_loss;
        out[2] = eik_loss;
        out[3] = ori_loss;
        out[4] = nori_loss;
        out[5] = gn_loss;
    }
}

extern "C" void kernel_launch(void* const* d_in, const int* in_sizes, int n_in,
                              void* d_out, int out_size)
{
    const float* manifold_pred    = (const float*)d_in[0];
    const float* manifold_grad    = (const float*)d_in[1];
    const float* nonmanifold_pred = (const float*)d_in[2];
    const float* near_points_pred = (const float*)d_in[3];
    const float* surface_points   = (const float*)d_in[4];
    const float* surface_normals  = (const float*)d_in[5];
    const float* off_surface_pts  = (const float*)d_in[6];
    const float* near_points      = (const float*)d_in[7];
    float* out = (float*)d_out;

    knn_kernel<<<KNN_BLK, TPB>>>(surface_points, off_surface_pts, near_points);
    merge_kernel<<<MRG_BLK, MRG_TPB>>>(manifold_pred, manifold_grad,
                                       nonmanifold_pred, near_points_pred,
                                       surface_points, surface_normals,
                                       off_surface_pts, near_points);
    finish_kernel<<<1, MRG_BLK>>>(out);
}